// round 8
// baseline (speedup 1.0000x reference)
#include <cuda_runtime.h>
#include <math.h>
#include <stdint.h>

// Problem constants
#define S_ 8192
#define D_ 2048
#define H_ 64
#define E_ 64
#define L_ 64

#define NPART 256
#define BM 64
#define BN 128
#define KC 32
#define NCH (D_ / KC)      // 64
#define RS 40              // smem row stride in bf16 elems (80 B, conflict-free ldsm)

// dynamic smem layout (bytes)
#define AHI_OFF 0
#define ALO_OFF 5120
#define BHI_OFF 10240
#define BLO_OFF 20480
#define BUF_STRIDE 30720
#define SMEM_DYN (2 * BUF_STRIDE)   // 61440; C overlay (32 KB) fits inside

// Static device scratch
__device__ __align__(16) float g_vpart[NPART][D_];
__device__ __align__(16) float g_v[D_];
__device__ float g_gate[2];
__device__ int   g_idx[2];

// ===========================================================================
// helpers
// ===========================================================================
__device__ __forceinline__ uint32_t smem_u32(const void* p) {
    uint32_t a;
    asm("{ .reg .u64 t; cvta.to.shared.u64 t, %1; cvt.u32.u64 %0, t; }"
        : "=r"(a) : "l"(p));
    return a;
}

// bf16 hi/lo split of 2 floats: hi = rn(f), lo = rn(f - hi), packed bf16x2
__device__ __forceinline__ void cvt_split(float f0, float f1, uint32_t& hi, uint32_t& lo) {
    uint32_t h;
    asm("cvt.rn.bf16x2.f32 %0, %1, %2;" : "=r"(h) : "f"(f1), "f"(f0));
    const float l0 = f0 - __uint_as_float(h << 16);
    const float l1 = f1 - __uint_as_float(h & 0xFFFF0000u);
    uint32_t l;
    asm("cvt.rn.bf16x2.f32 %0, %1, %2;" : "=r"(l) : "f"(l1), "f"(l0));
    hi = h; lo = l;
}

__device__ __forceinline__ void ldsm4(uint32_t* r, uint32_t addr) {
    asm volatile("ldmatrix.sync.aligned.m8n8.x4.shared.b16 {%0,%1,%2,%3}, [%4];"
                 : "=r"(r[0]), "=r"(r[1]), "=r"(r[2]), "=r"(r[3]) : "r"(addr));
}

__device__ __forceinline__ void mma_bf16(float* c, const uint32_t* a, const uint32_t* b) {
    asm volatile("mma.sync.aligned.m16n8k16.row.col.f32.bf16.bf16.f32 "
                 "{%0,%1,%2,%3}, {%4,%5,%6,%7}, {%8,%9}, {%0,%1,%2,%3};"
                 : "+f"(c[0]), "+f"(c[1]), "+f"(c[2]), "+f"(c[3])
                 : "r"(a[0]), "r"(a[1]), "r"(a[2]), "r"(a[3]), "r"(b[0]), "r"(b[1]));
}

__device__ __forceinline__ float gelu_exact(float v) {
    return 0.5f * v * (1.f + erff(v * 0.70710678118654752440f));
}

// ===========================================================================
// Kernel 1: weighted column sums: vpart[b][d] = sum_{32 rows} wout[s]*x[s][d]
// ===========================================================================
__global__ void __launch_bounds__(256) k_colsum(const float* __restrict__ x,
                                                const float* __restrict__ wout) {
    __shared__ float ws[32];
    const int b = blockIdx.x, t = threadIdx.x;
    const int row0 = b * 32;
    if (t < 32) ws[t] = wout[row0 + t];
    __syncthreads();

    const int d0 = t * 8;
    float acc[8];
#pragma unroll
    for (int i = 0; i < 8; i++) acc[i] = 0.f;
    const float* xp = x + (size_t)row0 * D_ + d0;
#pragma unroll 8
    for (int r = 0; r < 32; r++) {
        const float w = ws[r];
        const float4 a = *(const float4*)(xp);
        const float4 c = *(const float4*)(xp + 4);
        acc[0] = fmaf(w, a.x, acc[0]); acc[1] = fmaf(w, a.y, acc[1]);
        acc[2] = fmaf(w, a.z, acc[2]); acc[3] = fmaf(w, a.w, acc[3]);
        acc[4] = fmaf(w, c.x, acc[4]); acc[5] = fmaf(w, c.y, acc[5]);
        acc[6] = fmaf(w, c.z, acc[6]); acc[7] = fmaf(w, c.w, acc[7]);
        xp += D_;
    }
#pragma unroll
    for (int i = 0; i < 8; i++) g_vpart[b][d0 + i] = acc[i];
}

// ===========================================================================
// Kernel 2a: v[d] = sum_b vpart[b][d]
// ===========================================================================
__global__ void __launch_bounds__(256) k_vreduce() {
    const int d = blockIdx.x * 256 + threadIdx.x;
    float s = 0.f;
#pragma unroll 8
    for (int b = 0; b < NPART; b++) s += g_vpart[b][d];
    g_v[d] = s;
}

// ===========================================================================
// Kernel 2b: fused gate: u = Wg_in@v; scores = Wg_lin@u; top-2; softmax.
// One CTA, 512 threads.
// ===========================================================================
__global__ void __launch_bounds__(512) k_gate(const float* __restrict__ Wg_in,
                                              const float* __restrict__ Wg_lin) {
    __shared__ float v[D_];
    __shared__ float u[H_];
    __shared__ float sc[E_];
    const int t = threadIdx.x;
    for (int d = t; d < D_; d += 512) v[d] = g_v[d];
    __syncthreads();

    const int wid = t >> 5, lane = t & 31;
#pragma unroll
    for (int jj = 0; jj < 4; jj++) {
        const int j = wid * 4 + jj;
        const float* wr = Wg_in + (size_t)j * D_;
        float s = 0.f;
#pragma unroll
        for (int i = 0; i < 16; i++) {
            const float4 w = *(const float4*)(wr + i * 128 + lane * 4);
            const float4 vv = *(const float4*)(&v[i * 128 + lane * 4]);
            s += w.x * vv.x + w.y * vv.y + w.z * vv.z + w.w * vv.w;
        }
#pragma unroll
        for (int off = 16; off; off >>= 1) s += __shfl_down_sync(0xffffffffu, s, off);
        if (lane == 0) u[j] = s;
    }
    __syncthreads();

    if (t < E_) {
        float s = 0.f;
#pragma unroll
        for (int j = 0; j < H_; j++) s = fmaf(Wg_lin[t * H_ + j], u[j], s);
        sc[t] = s;
    }
    __syncthreads();

    if (t == 0) {
        int i0 = 0;
        for (int e = 1; e < E_; e++) if (sc[e] > sc[i0]) i0 = e;
        int i1 = (i0 == 0) ? 1 : 0;
        for (int e = 0; e < E_; e++) {
            if (e == i0 || e == i1) continue;
            if (sc[e] > sc[i1]) i1 = e;
        }
        const float e1 = expf(sc[i1] - sc[i0]);
        const float inv = 1.f / (1.f + e1);
        g_gate[0] = inv; g_gate[1] = e1 * inv;
        g_idx[0] = i0; g_idx[1] = i1;
    }
}

// ===========================================================================
// Kernel 3: HMMA expert GEMM (bf16 3-term split), inline fp32->bf16 split,
// double-buffered smem tiles (one sync per chunk), term-outermost MMA issue,
// fused normalize+GELU+combine epilogue.
//   CTA: 64 rows x 128 cols; 8 warps 2x4; warp = 32x32 via m16n8k16.
// ===========================================================================
__global__ void __launch_bounds__(256) k_expert(const float* __restrict__ x,
                                                const float* __restrict__ We,
                                                float* __restrict__ out) {
    extern __shared__ char dsm[];
    const uint32_t sbase = smem_u32(dsm);

    const int t = threadIdx.x;
    const int wid = t >> 5, lane = t & 31;
    const int row0 = blockIdx.x * BM;
    const int i0 = g_idx[0], i1 = g_idx[1];

    // ---- global load mapping (fp32 sources) ----
    const int arow = t & 63, akg = t >> 6;            // A: row, k-group of 8 floats
    const float* aptr = x + (size_t)(row0 + arow) * D_ + akg * 8;
    const int brow = t & 127, bkg = t >> 7;           // B: row, k-group of 16 floats
    const int be = (brow < 64) ? i0 : i1;
    const float* bptr = We + ((size_t)be * L_ + (brow & 63)) * D_ + bkg * 16;

    // STS element offsets within a tile (in uint16 units)
    const int aoff = arow * RS + akg * 8;
    const int boff = brow * RS + bkg * 16;

    // ---- fragment mapping ----
    const int warp_m = wid & 1, warp_n = wid >> 1;
    const int m_base = warp_m * 32, n_base = warp_n * 32;
    const int a_row = m_base + (lane & 15);
    const int a_k = (lane >> 4) << 3;
    const int b_row = n_base + ((lane >> 4) << 3) + (lane & 7);
    const int b_k = ((lane >> 3) & 1) << 3;

    const uint32_t fa = (uint32_t)(a_row * RS + a_k) * 2;
    const uint32_t fb = (uint32_t)(b_row * RS + b_k) * 2;

    float c[2][4][4];
#pragma unroll
    for (int mt = 0; mt < 2; mt++)
#pragma unroll
        for (int nt = 0; nt < 4; nt++)
#pragma unroll
            for (int r = 0; r < 4; r++) c[mt][nt][r] = 0.f;

    // ---- prologue: LDG chunk 0, convert, store into buffer 0 ----
    float4 pa0 = *(const float4*)(aptr);
    float4 pa1 = *(const float4*)(aptr + 4);
    float4 pb0 = *(const float4*)(bptr);
    float4 pb1 = *(const float4*)(bptr + 4);
    float4 pb2 = *(const float4*)(bptr + 8);
    float4 pb3 = *(const float4*)(bptr + 12);
    {
        uint16_t* Ahi = (uint16_t*)(dsm + AHI_OFF);
        uint16_t* Alo = (uint16_t*)(dsm + ALO_OFF);
        uint16_t* Bhi = (uint16_t*)(dsm + BHI_OFF);
        uint16_t* Blo = (uint16_t*)(dsm + BLO_OFF);
        uint4 hi, lo;
        cvt_split(pa0.x, pa0.y, hi.x, lo.x);
        cvt_split(pa0.z, pa0.w, hi.y, lo.y);
        cvt_split(pa1.x, pa1.y, hi.z, lo.z);
        cvt_split(pa1.z, pa1.w, hi.w, lo.w);
        *(uint4*)(Ahi + aoff) = hi;
        *(uint4*)(Alo + aoff) = lo;
        cvt_split(pb0.x, pb0.y, hi.x, lo.x);
        cvt_split(pb0.z, pb0.w, hi.y, lo.y);
        cvt_split(pb1.x, pb1.y, hi.z, lo.z);
        cvt_split(pb1.z, pb1.w, hi.w, lo.w);
        *(uint4*)(Bhi + boff) = hi;
        *(uint4*)(Blo + boff) = lo;
        cvt_split(pb2.x, pb2.y, hi.x, lo.x);
        cvt_split(pb2.z, pb2.w, hi.y, lo.y);
        cvt_split(pb3.x, pb3.y, hi.z, lo.z);
        cvt_split(pb3.z, pb3.w, hi.w, lo.w);
        *(uint4*)(Bhi + boff + 8) = hi;
        *(uint4*)(Blo + boff + 8) = lo;
    }
    __syncthreads();

#pragma unroll 1
    for (int ch = 0; ch < NCH; ++ch) {
        const int buf = ch & 1;
        const uint32_t tb = sbase + buf * BUF_STRIDE;

        // issue next chunk's LDGs first (latency hidden under MMAs)
        const bool more = (ch + 1 < NCH);
        if (more) {
            const float* ap = aptr + (ch + 1) * KC;
            pa0 = *(const float4*)(ap);
            pa1 = *(const float4*)(ap + 4);
            const float* bp = bptr + (ch + 1) * KC;
            pb0 = *(const float4*)(bp);
            pb1 = *(const float4*)(bp + 4);
            pb2 = *(const float4*)(bp + 8);
            pb3 = *(const float4*)(bp + 12);
        }

        // compute on current buffer: 2 k-steps of 16
#pragma unroll
        for (int ks = 0; ks < 2; ks++) {
            const uint32_t kb = ks * 32;   // 16 bf16 = 32 bytes
            uint32_t ahi[2][4], alo[2][4], bhi[2][4], blo[2][4];
#pragma unroll
            for (int mt = 0; mt < 2; mt++) {
                ldsm4(ahi[mt], tb + AHI_OFF + fa + mt * (16 * RS * 2) + kb);
                ldsm4(alo[mt], tb + ALO_OFF + fa + mt * (16 * RS * 2) + kb);
            }
#pragma unroll
            for (int nn = 0; nn < 2; nn++) {
                ldsm4(bhi[nn], tb + BHI_OFF + fb + nn * (16 * RS * 2) + kb);
                ldsm4(blo[nn], tb + BLO_OFF + fb + nn * (16 * RS * 2) + kb);
            }
            // term-outermost: 8 independent MMAs between accumulator reuses
#pragma unroll
            for (int mt = 0; mt < 2; mt++)
#pragma unroll
                for (int nt = 0; nt < 4; nt++)
                    mma_bf16(c[mt][nt], ahi[mt], &bhi[nt >> 1][(nt & 1) * 2]);
#pragma unroll
            for (int mt = 0; mt < 2; mt++)
#pragma unroll
                for (int nt = 0; nt < 4; nt++)
                    mma_bf16(c[mt][nt], alo[mt], &bhi[nt >> 1][(nt & 1) * 2]);
#pragma unroll
            for (int mt = 0; mt < 2; mt++)
#pragma unroll
                for (int nt = 0; nt < 4; nt++)
                    mma_bf16(c[mt][nt], ahi[mt], &blo[nt >> 1][(nt & 1) * 2]);
        }

        // convert + store next chunk into the other buffer
        if (more) {
            char* ob = dsm + (buf ^ 1) * BUF_STRIDE;
            uint16_t* Ahi = (uint16_t*)(ob + AHI_OFF);
            uint16_t* Alo = (uint16_t*)(ob + ALO_OFF);
            uint16_t* Bhi = (uint16_t*)(ob + BHI_OFF);
            uint16_t* Blo = (uint16_t*)(ob + BLO_OFF);
            uint4 hi, lo;
            cvt_split(pa0.x, pa0.y, hi.x, lo.x);
            cvt_split(pa0.z, pa0.w, hi.y, lo.y);
            cvt_split(pa1.x, pa1.y, hi.z, lo.z);
            cvt_split(pa1.z, pa1.w, hi.w, lo.w);
            *(uint4*)(Ahi + aoff) = hi;
            *(uint4*)(Alo + aoff) = lo;
            cvt_split(pb0.x, pb0.y, hi.x, lo.x);
            cvt_split(pb0.z, pb0.w, hi.y, lo.y);
            cvt_split(pb1.x, pb1.y, hi.z, lo.z);
            cvt_split(pb1.z, pb1.w, hi.w, lo.w);
            *(uint4*)(Bhi + boff) = hi;
            *(uint4*)(Blo + boff) = lo;
            cvt_split(pb2.x, pb2.y, hi.x, lo.x);
            cvt_split(pb2.z, pb2.w, hi.y, lo.y);
            cvt_split(pb3.x, pb3.y, hi.z, lo.z);
            cvt_split(pb3.z, pb3.w, hi.w, lo.w);
            *(uint4*)(Bhi + boff + 8) = hi;
            *(uint4*)(Blo + boff + 8) = lo;
        }
        __syncthreads();
    }

    // ---- stage C into smem (overlays tile space; all reads complete) ----
    float (*C)[BN] = (float (*)[BN])dsm;
#pragma unroll
    for (int mt = 0; mt < 2; mt++)
#pragma unroll
        for (int nt = 0; nt < 4; nt++) {
            const int r0 = m_base + mt * 16 + (lane >> 2);
            const int c0 = n_base + nt * 8 + 2 * (lane & 3);
            *(float2*)&C[r0][c0]     = make_float2(c[mt][nt][0], c[mt][nt][1]);
            *(float2*)&C[r0 + 8][c0] = make_float2(c[mt][nt][2], c[mt][nt][3]);
        }
    __syncthreads();

    // ---- epilogue: per-row L2 norm per expert half, GELU, gated combine ----
    const float g0 = g_gate[0], g1 = g_gate[1];
#pragma unroll
    for (int r = 0; r < 8; r++) {
        const int row = wid * 8 + r;
        const float z0a = C[row][lane];
        const float z0b = C[row][lane + 32];
        const float z1a = C[row][64 + lane];
        const float z1b = C[row][96 + lane];
        float ss0 = z0a * z0a + z0b * z0b;
        float ss1 = z1a * z1a + z1b * z1b;
#pragma unroll
        for (int off = 16; off; off >>= 1) {
            ss0 += __shfl_xor_sync(0xffffffffu, ss0, off);
            ss1 += __shfl_xor_sync(0xffffffffu, ss1, off);
        }
        const float inv0 = 1.f / fmaxf(sqrtf(ss0), 1e-12f);
        const float inv1 = 1.f / fmaxf(sqrtf(ss1), 1e-12f);
        float* orow = out + (size_t)(row0 + row) * L_;
        orow[lane]      = g0 * gelu_exact(z0a * inv0) + g1 * gelu_exact(z1a * inv1);
        orow[lane + 32] = g0 * gelu_exact(z0b * inv0) + g1 * gelu_exact(z1b * inv1);
    }
}

// ===========================================================================
extern "C" void kernel_launch(void* const* d_in, const int* in_sizes, int n_in,
                              void* d_out, int out_size) {
    const float* x      = (const float*)d_in[0];
    const float* Wg_in  = (const float*)d_in[1];
    const float* Wg_lin = (const float*)d_in[2];
    const float* Wg_out = (const float*)d_in[3];
    const float* We     = (const float*)d_in[4];
    float* out = (float*)d_out;

    cudaFuncSetAttribute(k_expert, cudaFuncAttributeMaxDynamicSharedMemorySize, SMEM_DYN);

    k_colsum<<<NPART, 256>>>(x, Wg_out);
    k_vreduce<<<8, 256>>>();
    k_gate<<<1, 512>>>(Wg_in, Wg_lin);
    k_expert<<<S_ / BM, 256, SMEM_DYN>>>(x, We, out);
}

// round 9
// speedup vs baseline: 1.7520x; 1.7520x over previous
#include <cuda_runtime.h>
#include <math.h>
#include <stdint.h>

// Problem constants
#define S_ 8192
#define D_ 2048
#define H_ 64
#define E_ 64
#define L_ 64

#define NPART 256
#define BM 64
#define BN 128
#define KC 32
#define NCH (D_ / KC)      // 64
#define RS 40              // smem row stride in bf16 (80 B, conflict-free ldsm)
#define NSTAGE 4

// dynamic smem stage layout (bytes)
#define AHI_OFF 0
#define ALO_OFF 5120
#define BHI_OFF 10240
#define BLO_OFF 20480
#define STAGE_BYTES 30720
#define SMEM_DYN (NSTAGE * STAGE_BYTES)   // 122880

// Static device scratch
__device__ __align__(16) float g_vpart[NPART][D_];
__device__ __align__(16) float g_v[D_];
__device__ float g_gate[2];
__device__ int   g_idx[2];
__device__ __align__(16) uint16_t g_xhi[S_][D_];       // 32 MB
__device__ __align__(16) uint16_t g_xlo[S_][D_];       // 32 MB
__device__ __align__(16) uint16_t g_whi[2 * L_][D_];   // 512 KB
__device__ __align__(16) uint16_t g_wlo[2 * L_][D_];

// ===========================================================================
// helpers
// ===========================================================================
__device__ __forceinline__ uint32_t smem_u32(const void* p) {
    uint32_t a;
    asm("{ .reg .u64 t; cvta.to.shared.u64 t, %1; cvt.u32.u64 %0, t; }"
        : "=r"(a) : "l"(p));
    return a;
}

__device__ __forceinline__ void cp16(uint32_t dst, const void* src) {
    asm volatile("cp.async.cg.shared.global [%0], [%1], 16;"
                 :: "r"(dst), "l"(src) : "memory");
}
#define CP_COMMIT() asm volatile("cp.async.commit_group;" ::: "memory")
#define CP_WAIT(n)  asm volatile("cp.async.wait_group %0;" :: "n"(n) : "memory")

// bf16 hi/lo split of 2 floats: hi = rn(f), lo = rn(f - hi), packed bf16x2
__device__ __forceinline__ void cvt_split(float f0, float f1, uint32_t& hi, uint32_t& lo) {
    uint32_t h;
    asm("cvt.rn.bf16x2.f32 %0, %1, %2;" : "=r"(h) : "f"(f1), "f"(f0));
    const float l0 = f0 - __uint_as_float(h << 16);
    const float l1 = f1 - __uint_as_float(h & 0xFFFF0000u);
    uint32_t l;
    asm("cvt.rn.bf16x2.f32 %0, %1, %2;" : "=r"(l) : "f"(l1), "f"(l0));
    hi = h; lo = l;
}

__device__ __forceinline__ void ldsm4(uint32_t* r, uint32_t addr) {
    asm volatile("ldmatrix.sync.aligned.m8n8.x4.shared.b16 {%0,%1,%2,%3}, [%4];"
                 : "=r"(r[0]), "=r"(r[1]), "=r"(r[2]), "=r"(r[3]) : "r"(addr));
}

__device__ __forceinline__ void mma_bf16(float* c, const uint32_t* a, const uint32_t* b) {
    asm volatile("mma.sync.aligned.m16n8k16.row.col.f32.bf16.bf16.f32 "
                 "{%0,%1,%2,%3}, {%4,%5,%6,%7}, {%8,%9}, {%0,%1,%2,%3};"
                 : "+f"(c[0]), "+f"(c[1]), "+f"(c[2]), "+f"(c[3])
                 : "r"(a[0]), "r"(a[1]), "r"(a[2]), "r"(a[3]), "r"(b[0]), "r"(b[1]));
}

__device__ __forceinline__ float gelu_exact(float v) {
    return 0.5f * v * (1.f + erff(v * 0.70710678118654752440f));
}

// ===========================================================================
// Kernel 1: fused weighted column-sum partials + bf16 hi/lo split of x.
// ===========================================================================
__global__ void __launch_bounds__(256) k_colsum_split(const float* __restrict__ x,
                                                      const float* __restrict__ wout) {
    __shared__ float ws[32];
    const int b = blockIdx.x, t = threadIdx.x;
    const int row0 = b * 32;
    if (t < 32) ws[t] = wout[row0 + t];
    __syncthreads();

    const int d0 = t * 8;
    float acc[8];
#pragma unroll
    for (int i = 0; i < 8; i++) acc[i] = 0.f;
    const float* xp = x + (size_t)row0 * D_ + d0;
#pragma unroll 4
    for (int r = 0; r < 32; r++) {
        const float w = ws[r];
        const float4 a = *(const float4*)(xp);
        const float4 c = *(const float4*)(xp + 4);
        acc[0] = fmaf(w, a.x, acc[0]); acc[1] = fmaf(w, a.y, acc[1]);
        acc[2] = fmaf(w, a.z, acc[2]); acc[3] = fmaf(w, a.w, acc[3]);
        acc[4] = fmaf(w, c.x, acc[4]); acc[5] = fmaf(w, c.y, acc[5]);
        acc[6] = fmaf(w, c.z, acc[6]); acc[7] = fmaf(w, c.w, acc[7]);
        uint4 hi, lo;
        cvt_split(a.x, a.y, hi.x, lo.x);
        cvt_split(a.z, a.w, hi.y, lo.y);
        cvt_split(c.x, c.y, hi.z, lo.z);
        cvt_split(c.z, c.w, hi.w, lo.w);
        *(uint4*)&g_xhi[row0 + r][d0] = hi;
        *(uint4*)&g_xlo[row0 + r][d0] = lo;
        xp += D_;
    }
#pragma unroll
    for (int i = 0; i < 8; i++) g_vpart[b][d0 + i] = acc[i];
}

// ===========================================================================
// Kernel 2a: v[d] = sum_b vpart[b][d]
// ===========================================================================
__global__ void __launch_bounds__(256) k_vreduce() {
    const int d = blockIdx.x * 256 + threadIdx.x;
    float s = 0.f;
#pragma unroll 8
    for (int b = 0; b < NPART; b++) s += g_vpart[b][d];
    g_v[d] = s;
}

// ===========================================================================
// Kernel 2b: fused gate: u = Wg_in@v; scores = Wg_lin@u; top-2; softmax.
// ===========================================================================
__global__ void __launch_bounds__(512) k_gate(const float* __restrict__ Wg_in,
                                              const float* __restrict__ Wg_lin) {
    __shared__ float v[D_];
    __shared__ float u[H_];
    __shared__ float sc[E_];
    const int t = threadIdx.x;
    for (int d = t; d < D_; d += 512) v[d] = g_v[d];
    __syncthreads();

    const int wid = t >> 5, lane = t & 31;
#pragma unroll
    for (int jj = 0; jj < 4; jj++) {
        const int j = wid * 4 + jj;
        const float* wr = Wg_in + (size_t)j * D_;
        float s = 0.f;
#pragma unroll
        for (int i = 0; i < 16; i++) {
            const float4 w = *(const float4*)(wr + i * 128 + lane * 4);
            const float4 vv = *(const float4*)(&v[i * 128 + lane * 4]);
            s += w.x * vv.x + w.y * vv.y + w.z * vv.z + w.w * vv.w;
        }
#pragma unroll
        for (int off = 16; off; off >>= 1) s += __shfl_down_sync(0xffffffffu, s, off);
        if (lane == 0) u[j] = s;
    }
    __syncthreads();

    if (t < E_) {
        float s = 0.f;
#pragma unroll
        for (int j = 0; j < H_; j++) s = fmaf(Wg_lin[t * H_ + j], u[j], s);
        sc[t] = s;
    }
    __syncthreads();

    if (t == 0) {
        int i0 = 0;
        for (int e = 1; e < E_; e++) if (sc[e] > sc[i0]) i0 = e;
        int i1 = (i0 == 0) ? 1 : 0;
        for (int e = 0; e < E_; e++) {
            if (e == i0 || e == i1) continue;
            if (sc[e] > sc[i1]) i1 = e;
        }
        const float e1 = expf(sc[i1] - sc[i0]);
        const float inv = 1.f / (1.f + e1);
        g_gate[0] = inv; g_gate[1] = e1 * inv;
        g_idx[0] = i0; g_idx[1] = i1;
    }
}

// ===========================================================================
// Kernel 2c: split the TWO selected experts' weights (grid 128 x 256).
// ===========================================================================
__global__ void __launch_bounds__(256) k_wsplit(const float* __restrict__ We) {
    const int r = blockIdx.x;
    const int t = threadIdx.x;
    const int e = (r < 64) ? g_idx[0] : g_idx[1];
    const float* src = We + ((size_t)e * L_ + (r & 63)) * D_ + t * 8;
    const float4 f0 = *(const float4*)(src);
    const float4 f1 = *(const float4*)(src + 4);
    uint4 hi, lo;
    cvt_split(f0.x, f0.y, hi.x, lo.x);
    cvt_split(f0.z, f0.w, hi.y, lo.y);
    cvt_split(f1.x, f1.y, hi.z, lo.z);
    cvt_split(f1.z, f1.w, hi.w, lo.w);
    *(uint4*)&g_whi[r][t * 8] = hi;
    *(uint4*)&g_wlo[r][t * 8] = lo;
}

// ===========================================================================
// Kernel 3: HMMA expert GEMM on pre-split bf16, cp.async 4-stage pipeline,
// term-outermost MMA issue, fused normalize+GELU+combine epilogue.
// ===========================================================================
__global__ void __launch_bounds__(256) k_expert(float* __restrict__ out) {
    extern __shared__ char dsm[];
    const uint32_t sbase = smem_u32(dsm);

    const int t = threadIdx.x;
    const int wid = t >> 5, lane = t & 31;
    const int row0 = blockIdx.x * BM;

    // ---- cp.async load mapping (16B segments) ----
    const int arow = t >> 2, aseg = t & 3;
    const uint16_t* gAhi = &g_xhi[row0 + arow][aseg * 8];
    const uint16_t* gAlo = &g_xlo[row0 + arow][aseg * 8];
    const uint32_t adst = (uint32_t)(arow * RS * 2 + aseg * 16);
    const uint16_t* gBhi[2]; const uint16_t* gBlo[2]; uint32_t bdst[2];
#pragma unroll
    for (int j = 0; j < 2; j++) {
        const int idx = j * 256 + t;
        const int br = idx >> 2, bs = idx & 3;
        gBhi[j] = &g_whi[br][bs * 8];
        gBlo[j] = &g_wlo[br][bs * 8];
        bdst[j] = (uint32_t)(br * RS * 2 + bs * 16);
    }

    // ---- fragment mapping ----
    const int warp_m = wid & 1, warp_n = wid >> 1;
    const int m_base = warp_m * 32, n_base = warp_n * 32;
    const int a_row = m_base + (lane & 15);
    const int a_k = (lane >> 4) << 3;
    const int b_row = n_base + ((lane >> 4) << 3) + (lane & 7);
    const int b_k = ((lane >> 3) & 1) << 3;
    const uint32_t fa = (uint32_t)(a_row * RS + a_k) * 2;
    const uint32_t fb = (uint32_t)(b_row * RS + b_k) * 2;

    float c[2][4][4];
#pragma unroll
    for (int mt = 0; mt < 2; mt++)
#pragma unroll
        for (int nt = 0; nt < 4; nt++)
#pragma unroll
            for (int r = 0; r < 4; r++) c[mt][nt][r] = 0.f;

    // ---- prologue: prefetch stages 0..2 ----
#pragma unroll
    for (int s = 0; s < NSTAGE - 1; s++) {
        const uint32_t sb = sbase + s * STAGE_BYTES;
        cp16(sb + AHI_OFF + adst, gAhi + s * KC);
        cp16(sb + ALO_OFF + adst, gAlo + s * KC);
#pragma unroll
        for (int j = 0; j < 2; j++) {
            cp16(sb + BHI_OFF + bdst[j], gBhi[j] + s * KC);
            cp16(sb + BLO_OFF + bdst[j], gBlo[j] + s * KC);
        }
        CP_COMMIT();
    }

#pragma unroll 1
    for (int ch = 0; ch < NCH; ++ch) {
        CP_WAIT(2);
        __syncthreads();

        const uint32_t tb = sbase + (ch & (NSTAGE - 1)) * STAGE_BYTES;
#pragma unroll
        for (int ks = 0; ks < 2; ks++) {
            const uint32_t kb = ks * 32;
            uint32_t ahi[2][4], alo[2][4], bhi[2][4], blo[2][4];
#pragma unroll
            for (int mt = 0; mt < 2; mt++) {
                ldsm4(ahi[mt], tb + AHI_OFF + fa + mt * (16 * RS * 2) + kb);
                ldsm4(alo[mt], tb + ALO_OFF + fa + mt * (16 * RS * 2) + kb);
            }
#pragma unroll
            for (int nn = 0; nn < 2; nn++) {
                ldsm4(bhi[nn], tb + BHI_OFF + fb + nn * (16 * RS * 2) + kb);
                ldsm4(blo[nn], tb + BLO_OFF + fb + nn * (16 * RS * 2) + kb);
            }
#pragma unroll
            for (int mt = 0; mt < 2; mt++)
#pragma unroll
                for (int nt = 0; nt < 4; nt++)
                    mma_bf16(c[mt][nt], ahi[mt], &bhi[nt >> 1][(nt & 1) * 2]);
#pragma unroll
            for (int mt = 0; mt < 2; mt++)
#pragma unroll
                for (int nt = 0; nt < 4; nt++)
                    mma_bf16(c[mt][nt], alo[mt], &bhi[nt >> 1][(nt & 1) * 2]);
#pragma unroll
            for (int mt = 0; mt < 2; mt++)
#pragma unroll
                for (int nt = 0; nt < 4; nt++)
                    mma_bf16(c[mt][nt], ahi[mt], &blo[nt >> 1][(nt & 1) * 2]);
        }

        const int pf = ch + NSTAGE - 1;
        if (pf < NCH) {
            const uint32_t sb = sbase + (pf & (NSTAGE - 1)) * STAGE_BYTES;
            cp16(sb + AHI_OFF + adst, gAhi + pf * KC);
            cp16(sb + ALO_OFF + adst, gAlo + pf * KC);
#pragma unroll
            for (int j = 0; j < 2; j++) {
                cp16(sb + BHI_OFF + bdst[j], gBhi[j] + pf * KC);
                cp16(sb + BLO_OFF + bdst[j], gBlo[j] + pf * KC);
            }
        }
        CP_COMMIT();
    }

    CP_WAIT(0);
    __syncthreads();

    // ---- stage C into smem (overlays stage space) ----
    float (*C)[BN] = (float (*)[BN])dsm;
#pragma unroll
    for (int mt = 0; mt < 2; mt++)
#pragma unroll
        for (int nt = 0; nt < 4; nt++) {
            const int r0 = m_base + mt * 16 + (lane >> 2);
            const int c0 = n_base + nt * 8 + 2 * (lane & 3);
            *(float2*)&C[r0][c0]     = make_float2(c[mt][nt][0], c[mt][nt][1]);
            *(float2*)&C[r0 + 8][c0] = make_float2(c[mt][nt][2], c[mt][nt][3]);
        }
    __syncthreads();

    // ---- epilogue ----
    const float g0 = g_gate[0], g1 = g_gate[1];
#pragma unroll
    for (int r = 0; r < 8; r++) {
        const int row = wid * 8 + r;
        const float z0a = C[row][lane];
        const float z0b = C[row][lane + 32];
        const float z1a = C[row][64 + lane];
        const float z1b = C[row][96 + lane];
        float ss0 = z0a * z0a + z0b * z0b;
        float ss1 = z1a * z1a + z1b * z1b;
#pragma unroll
        for (int off = 16; off; off >>= 1) {
            ss0 += __shfl_xor_sync(0xffffffffu, ss0, off);
            ss1 += __shfl_xor_sync(0xffffffffu, ss1, off);
        }
        const float inv0 = 1.f / fmaxf(sqrtf(ss0), 1e-12f);
        const float inv1 = 1.f / fmaxf(sqrtf(ss1), 1e-12f);
        float* orow = out + (size_t)(row0 + row) * L_;
        orow[lane]      = g0 * gelu_exact(z0a * inv0) + g1 * gelu_exact(z1a * inv1);
        orow[lane + 32] = g0 * gelu_exact(z0b * inv0) + g1 * gelu_exact(z1b * inv1);
    }
}

// ===========================================================================
extern "C" void kernel_launch(void* const* d_in, const int* in_sizes, int n_in,
                              void* d_out, int out_size) {
    const float* x      = (const float*)d_in[0];
    const float* Wg_in  = (const float*)d_in[1];
    const float* Wg_lin = (const float*)d_in[2];
    const float* Wg_out = (const float*)d_in[3];
    const float* We     = (const float*)d_in[4];
    float* out = (float*)d_out;

    cudaFuncSetAttribute(k_expert, cudaFuncAttributeMaxDynamicSharedMemorySize, SMEM_DYN);

    k_colsum_split<<<NPART, 256>>>(x, Wg_out);
    k_vreduce<<<8, 256>>>();
    k_gate<<<1, 512>>>(Wg_in, Wg_lin);
    k_wsplit<<<128, 256>>>(We);
    k_expert<<<S_ / BM, 256, SMEM_DYN>>>(out);
}